// round 2
// baseline (speedup 1.0000x reference)
#include <cuda_runtime.h>

#define SEQ 2048
#define NB 2
#define NH 16
#define AD 64
#define DM 1024
#define BH (NB*NH)
#define NPE 33

// Scratch (device globals — no allocation allowed)
__device__ float g_Q[(size_t)BH*SEQ*AD];      // head-major Q  [bh][s][64]
__device__ float g_K[(size_t)BH*SEQ*AD];
__device__ float g_V[(size_t)BH*SEQ*AD];
__device__ float g_P[(size_t)BH*SEQ*NPE];     // rel-bias projections
__device__ float g_S[(size_t)BH*SEQ*SEQ];     // scores / probs (512 MB)
__device__ float g_C[(size_t)NB*SEQ*DM];      // context, bqhd layout

// ---------------------------------------------------------------------------
// Generic tiled fp32 GEMM.  A row-major [M,K].  B row-major [K,N] (BT=false)
// or [N,K] (BT=true, computes A·Bᵀ).  Batched over blockIdx.z via strides.
// EPI: 0 = plain C[m*N+n]
//      1 = projection scatter -> head-major [b][h][s][d]   (m=b*S+s, n=h*64+d)
//      2 = scores: += relbias, *1/8, C += z*sC, Prel += z*SEQ*NPE
//      3 = ctx scatter -> [b][q][h][d]                      (z=b*H+h, n=d)
// ---------------------------------------------------------------------------
template<int BM,int BN,int BK,int TM,int TN,bool BT,int EPI>
__global__ __launch_bounds__((BM/TM)*(BN/TN))
void gemm_k(const float* __restrict__ A, const float* __restrict__ Bm,
            float* __restrict__ C, const float* __restrict__ Prel,
            int M, int N, int K, long sA, long sB, long sC)
{
    constexpr int THREADS = (BM/TM)*(BN/TN);
    __shared__ float As[BK][BM];
    __shared__ float Bs[BK][BN];

    const int z = blockIdx.z;
    A += (long)z * sA;
    Bm += (long)z * sB;
    C += (long)z * sC;

    const int tid = threadIdx.x;
    const int tx  = tid % (BN/TN);
    const int ty  = tid / (BN/TN);
    const int bm  = blockIdx.y * BM;
    const int bn  = blockIdx.x * BN;

    float acc[TM][TN] = {};

    for (int k0 = 0; k0 < K; k0 += BK) {
        // load A tile (transposed into As[k][m])
        #pragma unroll 1
        for (int i = tid; i < BM*BK/4; i += THREADS) {
            int r = i / (BK/4);
            int c = (i % (BK/4)) * 4;
            float4 v = *reinterpret_cast<const float4*>(A + (long)(bm + r)*K + k0 + c);
            As[c+0][r] = v.x; As[c+1][r] = v.y; As[c+2][r] = v.z; As[c+3][r] = v.w;
        }
        if constexpr (BT) {
            #pragma unroll 1
            for (int i = tid; i < BN*BK/4; i += THREADS) {
                int r = i / (BK/4);
                int c = (i % (BK/4)) * 4;
                float4 v = *reinterpret_cast<const float4*>(Bm + (long)(bn + r)*K + k0 + c);
                Bs[c+0][r] = v.x; Bs[c+1][r] = v.y; Bs[c+2][r] = v.z; Bs[c+3][r] = v.w;
            }
        } else {
            #pragma unroll 1
            for (int i = tid; i < BK*BN/4; i += THREADS) {
                int r = i / (BN/4);
                int c = (i % (BN/4)) * 4;
                *reinterpret_cast<float4*>(&Bs[r][c]) =
                    *reinterpret_cast<const float4*>(Bm + (long)(k0 + r)*N + bn + c);
            }
        }
        __syncthreads();

        #pragma unroll
        for (int kk = 0; kk < BK; kk++) {
            float af[TM], bf[TN];
            #pragma unroll
            for (int i = 0; i < TM; i++) af[i] = As[kk][ty*TM + i];
            #pragma unroll
            for (int j = 0; j < TN; j++) bf[j] = Bs[kk][tx*TN + j];
            #pragma unroll
            for (int i = 0; i < TM; i++)
                #pragma unroll
                for (int j = 0; j < TN; j++)
                    acc[i][j] += af[i] * bf[j];
        }
        __syncthreads();
    }

    // epilogue
    const float* Pz = (EPI == 2) ? (Prel + (long)z * SEQ * NPE) : Prel;
    #pragma unroll
    for (int i = 0; i < TM; i++) {
        const int m = bm + ty*TM + i;
        #pragma unroll
        for (int j = 0; j < TN; j++) {
            const int n = bn + tx*TN + j;
            float v = acc[i][j];
            if constexpr (EPI == 0) {
                C[(long)m * N + n] = v;
            } else if constexpr (EPI == 1) {
                int b = m / SEQ, s = m % SEQ;
                int h = n / AD,  d = n % AD;
                C[(((long)(b*NH + h))*SEQ + s)*AD + d] = v;
            } else if constexpr (EPI == 2) {
                int rel = n - m;
                rel = rel < -16 ? -16 : (rel > 16 ? 16 : rel);
                v = (v + Pz[m*NPE + rel + 16]) * 0.125f;
                C[(long)m * N + n] = v;
            } else { // EPI == 3
                int b = z / NH, h = z % NH;
                C[(((long)b*SEQ + m)*NH + h)*AD + n] = v;
            }
        }
    }
}

// Prel[bh*S+q][j] = dot(Qh[bh][q][:], rel_pemb[j][:])  for j in 0..32
__global__ __launch_bounds__(64)
void relproj_k(const float* __restrict__ Q, const float* __restrict__ pemb,
               float* __restrict__ P)
{
    __shared__ float qs[AD];
    const long row = blockIdx.x;
    qs[threadIdx.x] = Q[row*AD + threadIdx.x];
    __syncthreads();
    const int j = threadIdx.x;
    if (j < NPE) {
        float s = 0.f;
        #pragma unroll
        for (int d = 0; d < AD; d++) s += qs[d] * pemb[j*AD + d];
        P[row*NPE + j] = s;
    }
}

// Row softmax over SEQ=2048 elements, one block per row, 256 threads.
__global__ __launch_bounds__(256)
void softmax_k(float* __restrict__ S)
{
    const long row = blockIdx.x;
    float4* p = reinterpret_cast<float4*>(S + row * SEQ);
    const int t = threadIdx.x;
    float4 a = p[t], b = p[t + 256];

    float m = fmaxf(fmaxf(fmaxf(a.x, a.y), fmaxf(a.z, a.w)),
                    fmaxf(fmaxf(b.x, b.y), fmaxf(b.z, b.w)));
    #pragma unroll
    for (int o = 16; o > 0; o >>= 1) m = fmaxf(m, __shfl_xor_sync(0xffffffffu, m, o));

    __shared__ float red[8];
    const int wid = t >> 5, lane = t & 31;
    if (lane == 0) red[wid] = m;
    __syncthreads();
    float gm = red[0];
    #pragma unroll
    for (int i = 1; i < 8; i++) gm = fmaxf(gm, red[i]);
    __syncthreads();

    a.x = __expf(a.x - gm); a.y = __expf(a.y - gm);
    a.z = __expf(a.z - gm); a.w = __expf(a.w - gm);
    b.x = __expf(b.x - gm); b.y = __expf(b.y - gm);
    b.z = __expf(b.z - gm); b.w = __expf(b.w - gm);

    float s = a.x + a.y + a.z + a.w + b.x + b.y + b.z + b.w;
    #pragma unroll
    for (int o = 16; o > 0; o >>= 1) s += __shfl_xor_sync(0xffffffffu, s, o);
    if (lane == 0) red[wid] = s;
    __syncthreads();
    float gs = 0.f;
    #pragma unroll
    for (int i = 0; i < 8; i++) gs += red[i];

    const float inv = 1.f / gs;
    a.x *= inv; a.y *= inv; a.z *= inv; a.w *= inv;
    b.x *= inv; b.y *= inv; b.z *= inv; b.w *= inv;
    p[t] = a; p[t + 256] = b;
}

extern "C" void kernel_launch(void* const* d_in, const int* in_sizes, int n_in,
                              void* d_out, int out_size)
{
    const float* iQ   = (const float*)d_in[0];
    const float* iK   = (const float*)d_in[1];
    const float* iV   = (const float*)d_in[2];
    const float* Wq   = (const float*)d_in[3];
    const float* Wk   = (const float*)d_in[4];
    const float* Wv   = (const float*)d_in[5];
    const float* Wo   = (const float*)d_in[6];
    const float* pemb = (const float*)d_in[7];
    float* out = (float*)d_out;

    float *Q, *K, *V, *P, *S, *C;
    cudaGetSymbolAddress((void**)&Q, g_Q);
    cudaGetSymbolAddress((void**)&K, g_K);
    cudaGetSymbolAddress((void**)&V, g_V);
    cudaGetSymbolAddress((void**)&P, g_P);
    cudaGetSymbolAddress((void**)&S, g_S);
    cudaGetSymbolAddress((void**)&C, g_C);

    // 1) Projections -> head-major [b][h][s][d]
    dim3 gproj(DM/128, (NB*SEQ)/128, 1);
    gemm_k<128,128,8,8,8,false,1><<<gproj, 256>>>(iQ, Wq, Q, nullptr, NB*SEQ, DM, DM, 0, 0, 0);
    gemm_k<128,128,8,8,8,false,1><<<gproj, 256>>>(iK, Wk, K, nullptr, NB*SEQ, DM, DM, 0, 0, 0);
    gemm_k<128,128,8,8,8,false,1><<<gproj, 256>>>(iV, Wv, V, nullptr, NB*SEQ, DM, DM, 0, 0, 0);

    // 2) Rel-position bias projections P[bh,q,33] = q . rel_pemb[j]
    relproj_k<<<BH*SEQ, 64>>>(Q, pemb, P);

    // 3) Scores = Q Kᵀ (+relbias)/8, batched over bh
    dim3 gsc(SEQ/128, SEQ/128, BH);
    gemm_k<128,128,8,8,8,true,2><<<gsc, 256>>>(Q, K, S, P, SEQ, SEQ, AD,
                                               (long)SEQ*AD, (long)SEQ*AD, (long)SEQ*SEQ);

    // 4) Softmax over last dim
    softmax_k<<<BH*SEQ, 256>>>(S);

    // 5) ctx = probs @ V  -> [b][q][h][d]
    dim3 gpv(1, SEQ/128, BH);
    gemm_k<128,64,8,8,4,false,3><<<gpv, 256>>>(S, V, C, nullptr, SEQ, AD, SEQ,
                                               (long)SEQ*SEQ, (long)SEQ*AD, 0);

    // 6) out = ctx @ Wo
    gemm_k<128,128,8,8,8,false,0><<<gproj, 256>>>(C, Wo, out, nullptr, NB*SEQ, DM, DM, 0, 0, 0);
}